// round 1
// baseline (speedup 1.0000x reference)
#include <cuda_runtime.h>
#include <math.h>

// ---------------- problem constants ----------------
#define DMODEL  1024
#define DINNER  2048
#define DSTATE  16
#define DTRANK  64
#define DCONV   4
#define NB      4
#define LSEQ    2048
#define NLAYERS 4
#define NROWS   (NB * LSEQ)          // 8192 tokens
#define XPROJ_N (DTRANK + 2 * DSTATE) // 96

// ---------------- scratch (static device globals; no runtime allocation) ----
__device__ float g_xn  [(size_t)NROWS * DMODEL];      //  33.5 MB  LN output
__device__ float g_xz  [(size_t)NROWS * 2 * DINNER];  // 134   MB  in_proj out (xs | z)
__device__ float g_u   [(size_t)NROWS * DINNER];      //  67   MB  conv+silu out
__device__ float g_xdbl[(size_t)NROWS * XPROJ_N];     //   3   MB  x_proj out (dt_low|B|C)
__device__ float g_dt  [(size_t)NROWS * DINNER];      //  67   MB  softplus(dt)
__device__ float g_y   [(size_t)NROWS * DINNER];      //  67   MB  gated scan out
__device__ float g_x   [(size_t)NROWS * DMODEL];      //  33.5 MB  residual stream

// ---------------- LayerNorm: one block (256 thr) per row of 1024 -----------
__global__ void ln_kernel(const float* __restrict__ x,
                          const float* __restrict__ w,
                          const float* __restrict__ b,
                          float* __restrict__ out)
{
    const int row = blockIdx.x;
    const int tid = threadIdx.x;                 // 256 threads, 4 floats each
    const float4 v = reinterpret_cast<const float4*>(x + (size_t)row * DMODEL)[tid];

    float s  = v.x + v.y + v.z + v.w;
    float sq = v.x * v.x + v.y * v.y + v.z * v.z + v.w * v.w;
    #pragma unroll
    for (int o = 16; o; o >>= 1) {
        s  += __shfl_xor_sync(0xffffffffu, s,  o);
        sq += __shfl_xor_sync(0xffffffffu, sq, o);
    }
    __shared__ float ss[8], ssq[8];
    if ((tid & 31) == 0) { ss[tid >> 5] = s; ssq[tid >> 5] = sq; }
    __syncthreads();
    float ts = 0.f, tq = 0.f;
    #pragma unroll
    for (int i = 0; i < 8; i++) { ts += ss[i]; tq += ssq[i]; }

    const float mu  = ts * (1.f / DMODEL);
    const float var = tq * (1.f / DMODEL) - mu * mu;
    const float rs  = rsqrtf(var + 1e-5f);

    const float4 ww = reinterpret_cast<const float4*>(w)[tid];
    const float4 bb = reinterpret_cast<const float4*>(b)[tid];
    float4 o;
    o.x = (v.x - mu) * rs * ww.x + bb.x;
    o.y = (v.y - mu) * rs * ww.y + bb.y;
    o.z = (v.z - mu) * rs * ww.z + bb.z;
    o.w = (v.w - mu) * rs * ww.w + bb.w;
    reinterpret_cast<float4*>(out + (size_t)row * DMODEL)[tid] = o;
}

// ---------------- generic NT GEMM: C[M,N] = A[M,K] * B[N,K]^T --------------
// EPI: 0 = plain store, 1 = softplus(acc + bias[col]), 2 = acc + res[row,col]
template<int BM, int BN, int BK, int TM, int TN, int EPI>
__global__ void __launch_bounds__((BM / TM) * (BN / TN))
gemm_nt(const float* __restrict__ A, int lda,
        const float* __restrict__ B, int ldb,
        float* __restrict__ C, int ldc, int K,
        const float* __restrict__ bias, const float* __restrict__ res)
{
    constexpr int NT = (BM / TM) * (BN / TN);
    constexpr int TX = BN / TN;
    constexpr int AL = (BM * (BK / 4)) / NT;   // float4 loads of A per thread
    constexpr int BL = (BN * (BK / 4)) / NT;   // float4 loads of B per thread
    static_assert(AL * NT == BM * (BK / 4), "A tile load divisibility");
    static_assert(BL * NT == BN * (BK / 4), "B tile load divisibility");

    __shared__ float As[BK][BM + 4];
    __shared__ float Bs[BK][BN + 4];

    const int bm  = blockIdx.y * BM;
    const int bn  = blockIdx.x * BN;
    const int tid = threadIdx.x;
    const int tx  = tid % TX;
    const int ty  = tid / TX;

    float acc[TM][TN];
    #pragma unroll
    for (int i = 0; i < TM; i++)
        #pragma unroll
        for (int j = 0; j < TN; j++) acc[i][j] = 0.f;

    for (int k0 = 0; k0 < K; k0 += BK) {
        #pragma unroll
        for (int it = 0; it < AL; it++) {
            const int i = tid + it * NT;
            const int r = i / (BK / 4), c = i % (BK / 4);
            const float4 v = *reinterpret_cast<const float4*>(
                A + (size_t)(bm + r) * lda + k0 + c * 4);
            As[c * 4 + 0][r] = v.x; As[c * 4 + 1][r] = v.y;
            As[c * 4 + 2][r] = v.z; As[c * 4 + 3][r] = v.w;
        }
        #pragma unroll
        for (int it = 0; it < BL; it++) {
            const int i = tid + it * NT;
            const int r = i / (BK / 4), c = i % (BK / 4);
            const float4 v = *reinterpret_cast<const float4*>(
                B + (size_t)(bn + r) * ldb + k0 + c * 4);
            Bs[c * 4 + 0][r] = v.x; Bs[c * 4 + 1][r] = v.y;
            Bs[c * 4 + 2][r] = v.z; Bs[c * 4 + 3][r] = v.w;
        }
        __syncthreads();

        #pragma unroll
        for (int kk = 0; kk < BK; kk++) {
            float af[TM], bf[TN];
            if constexpr (TM % 4 == 0) {
                #pragma unroll
                for (int i = 0; i < TM / 4; i++)
                    *reinterpret_cast<float4*>(&af[i * 4]) =
                        *reinterpret_cast<const float4*>(&As[kk][ty * TM + i * 4]);
            } else {
                #pragma unroll
                for (int i = 0; i < TM; i++) af[i] = As[kk][ty * TM + i];
            }
            if constexpr (TN % 4 == 0) {
                #pragma unroll
                for (int j = 0; j < TN / 4; j++)
                    *reinterpret_cast<float4*>(&bf[j * 4]) =
                        *reinterpret_cast<const float4*>(&Bs[kk][tx * TN + j * 4]);
            } else {
                #pragma unroll
                for (int j = 0; j < TN; j++) bf[j] = Bs[kk][tx * TN + j];
            }
            #pragma unroll
            for (int i = 0; i < TM; i++)
                #pragma unroll
                for (int j = 0; j < TN; j++)
                    acc[i][j] = fmaf(af[i], bf[j], acc[i][j]);
        }
        __syncthreads();
    }

    #pragma unroll
    for (int i = 0; i < TM; i++) {
        const int r = bm + ty * TM + i;
        #pragma unroll
        for (int j = 0; j < TN; j++) {
            const int c = bn + tx * TN + j;
            float v = acc[i][j];
            if constexpr (EPI == 1) {
                v += bias[c];
                v = (v > 20.f) ? v : log1pf(__expf(v));   // softplus
            }
            if constexpr (EPI == 2) {
                v += res[(size_t)r * ldc + c];
            }
            C[(size_t)r * ldc + c] = v;
        }
    }
}

// ---------------- causal depthwise conv (width 4) + bias + SiLU ------------
__global__ void conv_silu_kernel(const float* __restrict__ cw,
                                 const float* __restrict__ cb)
{
    const size_t idx = (size_t)blockIdx.x * blockDim.x + threadIdx.x;
    if (idx >= (size_t)NROWS * DINNER) return;
    const int d   = (int)(idx % DINNER);
    const int row = (int)(idx / DINNER);      // b*L + t
    const int t   = row % LSEQ;

    const float w0 = cw[d * 4 + 0], w1 = cw[d * 4 + 1];
    const float w2 = cw[d * 4 + 2], w3 = cw[d * 4 + 3];

    float acc = cb[d];
    if (t >= 3) acc = fmaf(g_xz[(size_t)(row - 3) * (2 * DINNER) + d], w0, acc);
    if (t >= 2) acc = fmaf(g_xz[(size_t)(row - 2) * (2 * DINNER) + d], w1, acc);
    if (t >= 1) acc = fmaf(g_xz[(size_t)(row - 1) * (2 * DINNER) + d], w2, acc);
    acc = fmaf(g_xz[(size_t)row * (2 * DINNER) + d], w3, acc);

    const float sg = 1.f / (1.f + __expf(-acc));
    g_u[idx] = acc * sg;
}

// ---------------- selective scan, gated epilogue ---------------------------
// One thread per (batch, channel); 16-state vector in registers; sequential L.
// B_t / C_t are warp-uniform (same (b,t) across the warp) -> broadcast LDG.128.
__global__ void scan_kernel(const float* __restrict__ Alog,
                            const float* __restrict__ Dp)
{
    const int c = blockIdx.x * blockDim.x + threadIdx.x;  // 0..8191
    const int d = c % DINNER;
    const int b = c / DINNER;

    float A2[DSTATE];
    #pragma unroll
    for (int s = 0; s < DSTATE; s++)
        A2[s] = -__expf(Alog[d * DSTATE + s]) * 1.44269504f;  // A * log2(e)
    const float dp = Dp[d];

    float h[DSTATE];
    #pragma unroll
    for (int s = 0; s < DSTATE; s++) h[s] = 0.f;

    size_t row = (size_t)b * LSEQ;
    for (int t = 0; t < LSEQ; t++, row++) {
        const float dtv = g_dt[row * DINNER + d];
        const float uv  = g_u [row * DINNER + d];
        const float zv  = g_xz[row * (2 * DINNER) + DINNER + d];

        float BB[DSTATE], CC[DSTATE];
        const float4* p4 =
            reinterpret_cast<const float4*>(g_xdbl + row * XPROJ_N + DTRANK);
        #pragma unroll
        for (int q = 0; q < 4; q++) reinterpret_cast<float4*>(BB)[q] = p4[q];
        #pragma unroll
        for (int q = 0; q < 4; q++) reinterpret_cast<float4*>(CC)[q] = p4[4 + q];

        const float w = dtv * uv;
        float y = uv * dp;
        #pragma unroll
        for (int s = 0; s < DSTATE; s++) {
            const float dA = exp2f(dtv * A2[s]);
            h[s] = fmaf(dA, h[s], w * BB[s]);
            y    = fmaf(h[s], CC[s], y);
        }
        const float sg = 1.f / (1.f + __expf(-zv));
        g_y[row * DINNER + d] = y * (zv * sg);
    }
}

// ---------------- host orchestration ---------------------------------------
extern "C" void kernel_launch(void* const* d_in, const int* in_sizes, int n_in,
                              void* d_out, int out_size)
{
    const float* x     = (const float*)d_in[0];
    const float* W_in  = (const float*)d_in[1];
    const float* cw    = (const float*)d_in[2];
    const float* cb    = (const float*)d_in[3];
    const float* W_x   = (const float*)d_in[4];
    const float* W_dt  = (const float*)d_in[5];
    const float* b_dt  = (const float*)d_in[6];
    const float* Alog  = (const float*)d_in[7];
    const float* Dp    = (const float*)d_in[8];
    const float* W_out = (const float*)d_in[9];
    const float* lnw   = (const float*)d_in[10];
    const float* lnb   = (const float*)d_in[11];
    float* out = (float*)d_out;

    float *xn, *xz, *u, *xdbl, *dtb, *yb, *xs;
    cudaGetSymbolAddress((void**)&xn,   g_xn);
    cudaGetSymbolAddress((void**)&xz,   g_xz);
    cudaGetSymbolAddress((void**)&u,    g_u);
    cudaGetSymbolAddress((void**)&xdbl, g_xdbl);
    cudaGetSymbolAddress((void**)&dtb,  g_dt);
    cudaGetSymbolAddress((void**)&yb,   g_y);
    cudaGetSymbolAddress((void**)&xs,   g_x);

    for (int l = 0; l < NLAYERS; l++) {
        const float* xin = (l == 0) ? x : xs;

        // 1) LayerNorm
        ln_kernel<<<NROWS, 256>>>(xin, lnw + (size_t)l * DMODEL,
                                  lnb + (size_t)l * DMODEL, xn);

        // 2) in_proj: xz[8192,4096] = xn[8192,1024] @ W_in[4096,1024]^T
        gemm_nt<128, 128, 16, 8, 8, 0><<<dim3(2 * DINNER / 128, NROWS / 128), 256>>>(
            xn, DMODEL,
            W_in + (size_t)l * 2 * DINNER * DMODEL, DMODEL,
            xz, 2 * DINNER, DMODEL, nullptr, nullptr);

        // 3) causal depthwise conv + SiLU -> u
        conv_silu_kernel<<<(unsigned)(((size_t)NROWS * DINNER + 255) / 256), 256>>>(
            cw + (size_t)l * DINNER * DCONV, cb + (size_t)l * DINNER);

        // 4) x_proj: xdbl[8192,96] = u[8192,2048] @ W_x[96,2048]^T
        gemm_nt<64, 96, 32, 4, 6, 0><<<dim3(1, NROWS / 64), 256>>>(
            u, DINNER,
            W_x + (size_t)l * XPROJ_N * DINNER, DINNER,
            xdbl, XPROJ_N, DINNER, nullptr, nullptr);

        // 5) dt_proj + softplus: dt[8192,2048] = sp(xdbl[:, :64] @ W_dt^T + b_dt)
        gemm_nt<128, 128, 16, 8, 8, 1><<<dim3(DINNER / 128, NROWS / 128), 256>>>(
            xdbl, XPROJ_N,
            W_dt + (size_t)l * DINNER * DTRANK, DTRANK,
            dtb, DINNER, DTRANK,
            b_dt + (size_t)l * DINNER, nullptr);

        // 6) selective scan + D skip + SiLU(z) gate -> y
        scan_kernel<<<NB * DINNER / 128, 128>>>(
            Alog + (size_t)l * DINNER * DSTATE, Dp + (size_t)l * DINNER);

        // 7) out_proj + residual: x' = y @ W_out^T + xin
        float* tgt = (l == NLAYERS - 1) ? out : xs;
        gemm_nt<128, 128, 16, 8, 8, 2><<<dim3(DMODEL / 128, NROWS / 128), 256>>>(
            yb, DINNER,
            W_out + (size_t)l * DMODEL * DINNER, DINNER,
            tgt, DMODEL, DINNER,
            nullptr, xin);
    }
}

// round 3
// speedup vs baseline: 1.3371x; 1.3371x over previous
#include <cuda_runtime.h>
#include <cuda_bf16.h>
#include <math.h>
#include <stdint.h>

// ---------------- problem constants ----------------
#define DMODEL  1024
#define DINNER  2048
#define DSTATE  16
#define DTRANK  64
#define DCONV   4
#define NB      4
#define LSEQ    2048
#define NLAYERS 4
#define NROWS   (NB * LSEQ)           // 8192 tokens
#define XPROJ_N (DTRANK + 2 * DSTATE) // 96

// ---------------- scratch (static device globals; no runtime allocation) ----
__device__ float g_xn  [(size_t)NROWS * DMODEL];      // LN output
__device__ float g_xz  [(size_t)NROWS * 2 * DINNER];  // in_proj out (xs | z)
__device__ float g_u   [(size_t)NROWS * DINNER];      // conv+silu out
__device__ float g_xdbl[(size_t)NROWS * XPROJ_N];     // x_proj out (dt_low|B|C)
__device__ float g_dt  [(size_t)NROWS * DINNER];      // softplus(dt)
__device__ float g_y   [(size_t)NROWS * DINNER];      // gated scan out
__device__ float g_x   [(size_t)NROWS * DMODEL];      // residual stream

// bf16 hi/lo split scratch
__device__ __nv_bfloat16 g_ahi[(size_t)NROWS * DINNER];
__device__ __nv_bfloat16 g_alo[(size_t)NROWS * DINNER];
__device__ __nv_bfloat16 g_wih[(size_t)NLAYERS * 2 * DINNER * DMODEL];
__device__ __nv_bfloat16 g_wil[(size_t)NLAYERS * 2 * DINNER * DMODEL];
__device__ __nv_bfloat16 g_woh[(size_t)NLAYERS * DMODEL * DINNER];
__device__ __nv_bfloat16 g_wol[(size_t)NLAYERS * DMODEL * DINNER];

// ======================= PTX helpers (portable, no 'a' features) ===========
__device__ __forceinline__ void cp_async16(uint32_t dst, const void* src) {
    asm volatile("cp.async.cg.shared.global [%0], [%1], 16;"
                 :: "r"(dst), "l"(src));
}
__device__ __forceinline__ void ldsm4(uint32_t* r, uint32_t addr) {
    asm volatile("ldmatrix.sync.aligned.m8n8.x4.shared.b16 {%0,%1,%2,%3}, [%4];"
                 : "=r"(r[0]), "=r"(r[1]), "=r"(r[2]), "=r"(r[3]) : "r"(addr));
}
__device__ __forceinline__ void mma16816(float* d, const uint32_t* a,
                                         uint32_t b0, uint32_t b1) {
    asm volatile(
        "mma.sync.aligned.m16n8k16.row.col.f32.bf16.bf16.f32 "
        "{%0,%1,%2,%3}, {%4,%5,%6,%7}, {%8,%9}, {%0,%1,%2,%3};"
        : "+f"(d[0]), "+f"(d[1]), "+f"(d[2]), "+f"(d[3])
        : "r"(a[0]), "r"(a[1]), "r"(a[2]), "r"(a[3]), "r"(b0), "r"(b1));
}

// ======================= HMMA split-bf16 GEMM ==============================
// C[M,N] = A[M,K]*B[N,K]^T with A,B given as bf16 hi/lo pairs.
// CTA tile 128x128x32, 8 warps (4M x 2N), warp tile 32x64, mma m16n8k16.
// 3 MMAs per k-chunk: hi*hi + hi*lo + lo*hi (fp32 accum).
#define PITCH   80                        // 64B data + 16B pad (bank-safe)
#define TILE_B  (128 * PITCH)             // 10240 B
#define STAGE_B (4 * TILE_B)              // AHI|ALO|BHI|BLO = 40960 B
#define GM_SMEM (2 * STAGE_B)             // 81920 B

template<bool RES>
__global__ void __launch_bounds__(256, 1)
gemm_mma(const __nv_bfloat16* __restrict__ Ahi, const __nv_bfloat16* __restrict__ Alo,
         const __nv_bfloat16* __restrict__ Bhi, const __nv_bfloat16* __restrict__ Blo,
         int K, float* __restrict__ C, int ldc, const float* __restrict__ res)
{
    extern __shared__ char smem[];
    const uint32_t sb = (uint32_t)__cvta_generic_to_shared(smem);
    const int tid  = threadIdx.x;
    const int lane = tid & 31, wid = tid >> 5;
    const int bm = blockIdx.y * 128, bn = blockIdx.x * 128;
    const int wm = (wid & 3) * 32;        // warp M offset in tile
    const int wn = (wid >> 2) * 64;       // warp N offset in tile

    float acc[2][8][4];
    #pragma unroll
    for (int i = 0; i < 2; i++)
        #pragma unroll
        for (int j = 0; j < 8; j++)
            #pragma unroll
            for (int q = 0; q < 4; q++) acc[i][j][q] = 0.f;

    // ldmatrix per-lane offsets
    const int rowA = lane & 15, chA = lane >> 4;          // A: rows m, chunks k
    const uint32_t aoff = (uint32_t)((wm + rowA) * PITCH + chA * 16);
    const int rowB = (lane & 7) + ((lane >> 4) << 3);     // B: rows n
    const int chB  = (lane >> 3) & 1;                     // chunks k
    const uint32_t boff = (uint32_t)((wn + rowB) * PITCH + chB * 16);

    const __nv_bfloat16* gsrc[4] = {Ahi, Alo, Bhi, Blo};

    // ---- stage loader: 4 tiles x 128 rows x 4 x 16B chunks via cp.async ----
    auto load_stage = [&](int stg, int k0) {
        const uint32_t base = sb + stg * STAGE_B;
        #pragma unroll
        for (int j = 0; j < 8; j++) {
            const int tile = j >> 1;                       // compile-time
            const int rc   = tid + (j & 1) * 256;          // 0..511
            const int row  = rc >> 2, c = rc & 3;
            const int row0 = (tile < 2) ? bm : bn;
            const uint32_t dst = base + tile * TILE_B + row * PITCH + c * 16;
            const void* src = gsrc[tile] + (size_t)(row0 + row) * K + k0 + c * 8;
            cp_async16(dst, src);
        }
        asm volatile("cp.async.commit_group;");
    };

    // ---- compute one 32-K stage ----
    auto compute_stage = [&](int stg) {
        const uint32_t base = sb + stg * STAGE_B;
        #pragma unroll
        for (int k16 = 0; k16 < 2; k16++) {
            uint32_t ah[2][4], al[2][4], bh[4][4], bl[4][4];
            #pragma unroll
            for (int mi = 0; mi < 2; mi++) {
                ldsm4(ah[mi], base + 0 * TILE_B + aoff + mi * (16 * PITCH) + k16 * 32);
                ldsm4(al[mi], base + 1 * TILE_B + aoff + mi * (16 * PITCH) + k16 * 32);
            }
            #pragma unroll
            for (int nj = 0; nj < 4; nj++) {
                ldsm4(bh[nj], base + 2 * TILE_B + boff + nj * (16 * PITCH) + k16 * 32);
                ldsm4(bl[nj], base + 3 * TILE_B + boff + nj * (16 * PITCH) + k16 * 32);
            }
            #pragma unroll
            for (int mi = 0; mi < 2; mi++)
                #pragma unroll
                for (int ni = 0; ni < 8; ni++) {
                    const uint32_t h0 = bh[ni >> 1][(ni & 1) * 2];
                    const uint32_t h1 = bh[ni >> 1][(ni & 1) * 2 + 1];
                    const uint32_t l0 = bl[ni >> 1][(ni & 1) * 2];
                    const uint32_t l1 = bl[ni >> 1][(ni & 1) * 2 + 1];
                    mma16816(acc[mi][ni], ah[mi], h0, h1);
                    mma16816(acc[mi][ni], ah[mi], l0, l1);
                    mma16816(acc[mi][ni], al[mi], h0, h1);
                }
        }
    };

    // ---- pipelined main loop ----
    load_stage(0, 0);
    const int nK = K >> 5;
    for (int ks = 0; ks < nK; ks++) {
        if (ks + 1 < nK) {
            load_stage((ks + 1) & 1, (ks + 1) * 32);
            asm volatile("cp.async.wait_group 1;");
        } else {
            asm volatile("cp.async.wait_group 0;");
        }
        __syncthreads();
        compute_stage(ks & 1);
        __syncthreads();
    }

    // ---- epilogue: regs -> gmem (optional residual) ----
    #pragma unroll
    for (int mi = 0; mi < 2; mi++)
        #pragma unroll
        for (int ni = 0; ni < 8; ni++) {
            const int r0 = bm + wm + mi * 16 + (lane >> 2);
            const int cc = bn + wn + ni * 8 + (lane & 3) * 2;
            float2 v0 = make_float2(acc[mi][ni][0], acc[mi][ni][1]);
            float2 v1 = make_float2(acc[mi][ni][2], acc[mi][ni][3]);
            if (RES) {
                const float2 a0 = *reinterpret_cast<const float2*>(
                    res + (size_t)r0 * ldc + cc);
                const float2 a1 = *reinterpret_cast<const float2*>(
                    res + (size_t)(r0 + 8) * ldc + cc);
                v0.x += a0.x; v0.y += a0.y;
                v1.x += a1.x; v1.y += a1.y;
            }
            *reinterpret_cast<float2*>(C + (size_t)r0 * ldc + cc) = v0;
            *reinterpret_cast<float2*>(C + (size_t)(r0 + 8) * ldc + cc) = v1;
        }
}

// ---------------- fp32 -> bf16 hi/lo split ---------------------------------
__global__ void cvt_split(const float4* __restrict__ src,
                          uint32_t* __restrict__ hi, uint32_t* __restrict__ lo,
                          int n4)
{
    const int i = blockIdx.x * blockDim.x + threadIdx.x;
    if (i >= n4) return;
    const float4 v = src[i];
    __nv_bfloat162 ha = __floats2bfloat162_rn(v.x, v.y);
    __nv_bfloat162 hb = __floats2bfloat162_rn(v.z, v.w);
    float2 fa = __bfloat1622float2(ha), fb = __bfloat1622float2(hb);
    __nv_bfloat162 la = __floats2bfloat162_rn(v.x - fa.x, v.y - fa.y);
    __nv_bfloat162 lb = __floats2bfloat162_rn(v.z - fb.x, v.w - fb.y);
    uint2 hp, lp;
    hp.x = *reinterpret_cast<uint32_t*>(&ha); hp.y = *reinterpret_cast<uint32_t*>(&hb);
    lp.x = *reinterpret_cast<uint32_t*>(&la); lp.y = *reinterpret_cast<uint32_t*>(&lb);
    reinterpret_cast<uint2*>(hi)[i] = hp;
    reinterpret_cast<uint2*>(lo)[i] = lp;
}

// ---------------- LayerNorm ------------------------------------------------
__global__ void ln_kernel(const float* __restrict__ x,
                          const float* __restrict__ w,
                          const float* __restrict__ b,
                          float* __restrict__ out)
{
    const int row = blockIdx.x;
    const int tid = threadIdx.x;
    const float4 v = reinterpret_cast<const float4*>(x + (size_t)row * DMODEL)[tid];

    float s  = v.x + v.y + v.z + v.w;
    float sq = v.x * v.x + v.y * v.y + v.z * v.z + v.w * v.w;
    #pragma unroll
    for (int o = 16; o; o >>= 1) {
        s  += __shfl_xor_sync(0xffffffffu, s,  o);
        sq += __shfl_xor_sync(0xffffffffu, sq, o);
    }
    __shared__ float ss[8], ssq[8];
    if ((tid & 31) == 0) { ss[tid >> 5] = s; ssq[tid >> 5] = sq; }
    __syncthreads();
    float ts = 0.f, tq = 0.f;
    #pragma unroll
    for (int i = 0; i < 8; i++) { ts += ss[i]; tq += ssq[i]; }

    const float mu  = ts * (1.f / DMODEL);
    const float var = tq * (1.f / DMODEL) - mu * mu;
    const float rs  = rsqrtf(var + 1e-5f);

    const float4 ww = reinterpret_cast<const float4*>(w)[tid];
    const float4 bb = reinterpret_cast<const float4*>(b)[tid];
    float4 o;
    o.x = (v.x - mu) * rs * ww.x + bb.x;
    o.y = (v.y - mu) * rs * ww.y + bb.y;
    o.z = (v.z - mu) * rs * ww.z + bb.z;
    o.w = (v.w - mu) * rs * ww.w + bb.w;
    reinterpret_cast<float4*>(out + (size_t)row * DMODEL)[tid] = o;
}

// ---------------- SIMT NT GEMM (small K: x_proj, dt_proj) ------------------
// EPI: 0 = plain store, 1 = softplus(acc + bias[col])
template<int BM, int BN, int BK, int TM, int TN, int EPI>
__global__ void __launch_bounds__((BM / TM) * (BN / TN))
gemm_nt(const float* __restrict__ A, int lda,
        const float* __restrict__ B, int ldb,
        float* __restrict__ C, int ldc, int K,
        const float* __restrict__ bias)
{
    constexpr int NT = (BM / TM) * (BN / TN);
    constexpr int TX = BN / TN;
    constexpr int AL = (BM * (BK / 4)) / NT;
    constexpr int BL = (BN * (BK / 4)) / NT;

    __shared__ float As[BK][BM + 4];
    __shared__ float Bs[BK][BN + 4];

    const int bm  = blockIdx.y * BM;
    const int bn  = blockIdx.x * BN;
    const int tid = threadIdx.x;
    const int tx  = tid % TX;
    const int ty  = tid / TX;

    float acc[TM][TN];
    #pragma unroll
    for (int i = 0; i < TM; i++)
        #pragma unroll
        for (int j = 0; j < TN; j++) acc[i][j] = 0.f;

    for (int k0 = 0; k0 < K; k0 += BK) {
        #pragma unroll
        for (int it = 0; it < AL; it++) {
            const int i = tid + it * NT;
            const int r = i / (BK / 4), c = i % (BK / 4);
            const float4 v = *reinterpret_cast<const float4*>(
                A + (size_t)(bm + r) * lda + k0 + c * 4);
            As[c * 4 + 0][r] = v.x; As[c * 4 + 1][r] = v.y;
            As[c * 4 + 2][r] = v.z; As[c * 4 + 3][r] = v.w;
        }
        #pragma unroll
        for (int it = 0; it < BL; it++) {
            const int i = tid + it * NT;
            const int r = i / (BK / 4), c = i % (BK / 4);
            const float4 v = *reinterpret_cast<const float4*>(
                B + (size_t)(bn + r) * ldb + k0 + c * 4);
            Bs[c * 4 + 0][r] = v.x; Bs[c * 4 + 1][r] = v.y;
            Bs[c * 4 + 2][r] = v.z; Bs[c * 4 + 3][r] = v.w;
        }
        __syncthreads();

        #pragma unroll
        for (int kk = 0; kk < BK; kk++) {
            float af[TM], bf[TN];
            #pragma unroll
            for (int i = 0; i < TM; i++) af[i] = As[kk][ty * TM + i];
            #pragma unroll
            for (int j = 0; j < TN; j++) bf[j] = Bs[kk][tx * TN + j];
            #pragma unroll
            for (int i = 0; i < TM; i++)
                #pragma unroll
                for (int j = 0; j < TN; j++)
                    acc[i][j] = fmaf(af[i], bf[j], acc[i][j]);
        }
        __syncthreads();
    }

    #pragma unroll
    for (int i = 0; i < TM; i++) {
        const int r = bm + ty * TM + i;
        #pragma unroll
        for (int j = 0; j < TN; j++) {
            const int c = bn + tx * TN + j;
            float v = acc[i][j];
            if constexpr (EPI == 1) {
                v += bias[c];
                v = (v > 20.f) ? v : log1pf(__expf(v));
            }
            C[(size_t)r * ldc + c] = v;
        }
    }
}

// ---------------- causal depthwise conv (width 4) + bias + SiLU ------------
__global__ void conv_silu_kernel(const float* __restrict__ cw,
                                 const float* __restrict__ cb)
{
    const size_t idx = (size_t)blockIdx.x * blockDim.x + threadIdx.x;
    if (idx >= (size_t)NROWS * DINNER) return;
    const int d   = (int)(idx % DINNER);
    const int row = (int)(idx / DINNER);
    const int t   = row % LSEQ;

    const float w0 = cw[d * 4 + 0], w1 = cw[d * 4 + 1];
    const float w2 = cw[d * 4 + 2], w3 = cw[d * 4 + 3];

    float acc = cb[d];
    if (t >= 3) acc = fmaf(g_xz[(size_t)(row - 3) * (2 * DINNER) + d], w0, acc);
    if (t >= 2) acc = fmaf(g_xz[(size_t)(row - 2) * (2 * DINNER) + d], w1, acc);
    if (t >= 1) acc = fmaf(g_xz[(size_t)(row - 1) * (2 * DINNER) + d], w2, acc);
    acc = fmaf(g_xz[(size_t)row * (2 * DINNER) + d], w3, acc);

    const float sg = 1.f / (1.f + __expf(-acc));
    g_u[idx] = acc * sg;
}

// ---------------- selective scan, gated epilogue ---------------------------
__global__ void scan_kernel(const float* __restrict__ Alog,
                            const float* __restrict__ Dp)
{
    const int c = blockIdx.x * blockDim.x + threadIdx.x;
    const int d = c % DINNER;
    const int b = c / DINNER;

    float A2[DSTATE];
    #pragma unroll
    for (int s = 0; s < DSTATE; s++)
        A2[s] = -__expf(Alog[d * DSTATE + s]) * 1.44269504f;
    const float dp = Dp[d];

    float h[DSTATE];
    #pragma unroll
    for (int s = 0; s < DSTATE; s++) h[s] = 0.f;

    size_t row = (size_t)b * LSEQ;
    for (int t = 0; t < LSEQ; t++, row++) {
        const float dtv = g_dt[row * DINNER + d];
        const float uv  = g_u [row * DINNER + d];
        const float zv  = g_xz[row * (2 * DINNER) + DINNER + d];

        float BB[DSTATE], CC[DSTATE];
        const float4* p4 =
            reinterpret_cast<const float4*>(g_xdbl + row * XPROJ_N + DTRANK);
        #pragma unroll
        for (int q = 0; q < 4; q++) reinterpret_cast<float4*>(BB)[q] = p4[q];
        #pragma unroll
        for (int q = 0; q < 4; q++) reinterpret_cast<float4*>(CC)[q] = p4[4 + q];

        const float w = dtv * uv;
        float y = uv * dp;
        #pragma unroll
        for (int s = 0; s < DSTATE; s++) {
            const float dA = exp2f(dtv * A2[s]);
            h[s] = fmaf(dA, h[s], w * BB[s]);
            y    = fmaf(h[s], CC[s], y);
        }
        const float sg = 1.f / (1.f + __expf(-zv));
        g_y[row * DINNER + d] = y * (zv * sg);
    }
}

// ---------------- host orchestration ---------------------------------------
extern "C" void kernel_launch(void* const* d_in, const int* in_sizes, int n_in,
                              void* d_out, int out_size)
{
    const float* x     = (const float*)d_in[0];
    const float* W_in  = (const float*)d_in[1];
    const float* cw    = (const float*)d_in[2];
    const float* cb    = (const float*)d_in[3];
    const float* W_x   = (const float*)d_in[4];
    const float* W_dt  = (const float*)d_in[5];
    const float* b_dt  = (const float*)d_in[6];
    const float* Alog  = (const float*)d_in[7];
    const float* Dp    = (const float*)d_in[8];
    const float* W_out = (const float*)d_in[9];
    const float* lnw   = (const float*)d_in[10];
    const float* lnb   = (const float*)d_in[11];
    float* out = (float*)d_out;

    float *xn, *xz, *u, *xdbl, *dtb, *yb, *xs;
    __nv_bfloat16 *ahi, *alo, *wih, *wil, *woh, *wol;
    cudaGetSymbolAddress((void**)&xn,   g_xn);
    cudaGetSymbolAddress((void**)&xz,   g_xz);
    cudaGetSymbolAddress((void**)&u,    g_u);
    cudaGetSymbolAddress((void**)&xdbl, g_xdbl);
    cudaGetSymbolAddress((void**)&dtb,  g_dt);
    cudaGetSymbolAddress((void**)&yb,   g_y);
    cudaGetSymbolAddress((void**)&xs,   g_x);
    cudaGetSymbolAddress((void**)&ahi,  g_ahi);
    cudaGetSymbolAddress((void**)&alo,  g_alo);
    cudaGetSymbolAddress((void**)&wih,  g_wih);
    cudaGetSymbolAddress((void**)&wil,  g_wil);
    cudaGetSymbolAddress((void**)&woh,  g_woh);
    cudaGetSymbolAddress((void**)&wol,  g_wol);

    cudaFuncSetAttribute(gemm_mma<false>,
                         cudaFuncAttributeMaxDynamicSharedMemorySize, GM_SMEM);
    cudaFuncSetAttribute(gemm_mma<true>,
                         cudaFuncAttributeMaxDynamicSharedMemorySize, GM_SMEM);

    // split ALL layer weights to bf16 hi/lo (same work every call)
    {
        int w4 = NLAYERS * 2 * DINNER * DMODEL / 4;
        cvt_split<<<(w4 + 255) / 256, 256>>>((const float4*)W_in,
                                             (uint32_t*)wih, (uint32_t*)wil, w4);
        int o4 = NLAYERS * DMODEL * DINNER / 4;
        cvt_split<<<(o4 + 255) / 256, 256>>>((const float4*)W_out,
                                             (uint32_t*)woh, (uint32_t*)wol, o4);
    }

    for (int l = 0; l < NLAYERS; l++) {
        const float* xin = (l == 0) ? x : xs;
        const size_t wiOff = (size_t)l * 2 * DINNER * DMODEL;
        const size_t woOff = (size_t)l * DMODEL * DINNER;

        // 1) LayerNorm
        ln_kernel<<<NROWS, 256>>>(xin, lnw + (size_t)l * DMODEL,
                                  lnb + (size_t)l * DMODEL, xn);

        // 2) split LN activations to bf16 hi/lo
        {
            int n4 = NROWS * DMODEL / 4;
            cvt_split<<<(n4 + 255) / 256, 256>>>((const float4*)xn,
                                                 (uint32_t*)ahi, (uint32_t*)alo, n4);
        }

        // 3) in_proj (HMMA): xz[8192,4096] = xn @ W_in^T
        gemm_mma<false><<<dim3(2 * DINNER / 128, NROWS / 128), 256, GM_SMEM>>>(
            ahi, alo, wih + wiOff, wil + wiOff, DMODEL, xz, 2 * DINNER, nullptr);

        // 4) causal depthwise conv + SiLU -> u
        conv_silu_kernel<<<(unsigned)(((size_t)NROWS * DINNER + 255) / 256), 256>>>(
            cw + (size_t)l * DINNER * DCONV, cb + (size_t)l * DINNER);

        // 5) x_proj (SIMT): xdbl[8192,96] = u @ W_x^T
        gemm_nt<64, 96, 32, 4, 6, 0><<<dim3(1, NROWS / 64), 256>>>(
            u, DINNER,
            W_x + (size_t)l * XPROJ_N * DINNER, DINNER,
            xdbl, XPROJ_N, DINNER, nullptr);

        // 6) dt_proj + softplus (SIMT, K=64)
        gemm_nt<128, 128, 16, 8, 8, 1><<<dim3(DINNER / 128, NROWS / 128), 256>>>(
            xdbl, XPROJ_N,
            W_dt + (size_t)l * DINNER * DTRANK, DTRANK,
            dtb, DINNER, DTRANK,
            b_dt + (size_t)l * DINNER);

        // 7) selective scan + D skip + SiLU(z) gate -> y
        scan_kernel<<<NB * DINNER / 128, 128>>>(
            Alog + (size_t)l * DINNER * DSTATE, Dp + (size_t)l * DINNER);

        // 8) split scan output to bf16 hi/lo
        {
            int n4 = NROWS * DINNER / 4;
            cvt_split<<<(n4 + 255) / 256, 256>>>((const float4*)yb,
                                                 (uint32_t*)ahi, (uint32_t*)alo, n4);
        }

        // 9) out_proj + residual (HMMA): x' = y @ W_out^T + xin
        float* tgt = (l == NLAYERS - 1) ? out : xs;
        gemm_mma<true><<<dim3(DMODEL / 128, NROWS / 128), 256, GM_SMEM>>>(
            ahi, alo, woh + woOff, wol + woOff, DINNER, tgt, DMODEL, xin);
    }
}